// round 6
// baseline (speedup 1.0000x reference)
#include <cuda_runtime.h>

// TrigoLinear: out[b,o] = sum_i sin(x[b,i]*w_sin[o,i] + b_sin[o,i]) * w_out[o,i] + b_out[o]
// Hybrid: oo 0,1 scalar MUFU path; oo 2,3 packed f32x2 Taylor-5 path.
// Zero pack/unpack MOVs: packed operands come directly from LDS.64 (float2/ull union),
// and x is stored duplicated in smem so the broadcast pair is a single LDS.64.

#define B_DIM   1024
#define IN_DIM  512
#define OUT_DIM 512

#define BM 64
#define BN 64
#define BK 32
#define PAD  68    // o-side row stride (floats)
#define PAD2 132   // duplicated-x row stride (floats): 64 float2 slots + pad

typedef unsigned long long ull;

union F2U { float2 f; ull u; };

__device__ __forceinline__ ull fma2_(ull a, ull b, ull c) {
    ull d; asm("fma.rn.f32x2 %0, %1, %2, %3;" : "=l"(d) : "l"(a), "l"(b), "l"(c)); return d;
}
__device__ __forceinline__ ull mul2_(ull a, ull b) {
    ull d; asm("mul.rn.f32x2 %0, %1, %2;" : "=l"(d) : "l"(a), "l"(b)); return d;
}
__device__ __forceinline__ float sin_mufu(float a) {
    float d; asm("sin.approx.f32 %0, %1;" : "=f"(d) : "f"(a)); return d;
}
__device__ __forceinline__ ull pkc(float c) {  // compile-time constant pack (hoisted)
    F2U t; t.f = make_float2(c, c); return t.u;
}

__global__ __launch_bounds__(256, 1)
void trigo_kernel(const float* __restrict__ x,
                  const float* __restrict__ weight,
                  const float* __restrict__ bias,
                  float* __restrict__ out) {
    __shared__ __align__(16) float sx2[BK * PAD2];  // [k][b] duplicated {x,x}
    __shared__ __align__(16) float sws[BK * PAD];   // [k][o] w_sin
    __shared__ __align__(16) float sbs[BK * PAD];   // [k][o] b_sin
    __shared__ __align__(16) float swo[BK * PAD];   // [k][o] w_out

    const int tid = threadIdx.x;
    const int tx = tid & 15;   // 4 outs/thread: o = tx*4
    const int ty = tid >> 4;   // 4 rows/thread: b = ty*4
    const int bRow = blockIdx.y * BM;
    const int oCol = blockIdx.x * BN;

    const float2* __restrict__ w2 = (const float2*)weight;

    // register staging (software pipeline)
    float  rx[8];
    float2 rw[8];
    float  rb[8];

    // ---- prologue: tile 0 ----
    #pragma unroll
    for (int j = 0; j < 8; j++) {
        int idx = tid + j * 256;
        int r = idx >> 5, k = idx & 31;
        rx[j] = x[(bRow + r) * IN_DIM + k];
        rw[j] = w2[(oCol + r) * IN_DIM + k];
        rb[j] = bias[(oCol + r) * (IN_DIM + 1) + k];
    }
    #pragma unroll
    for (int j = 0; j < 8; j++) {
        int idx = tid + j * 256;
        int r = idx >> 5, k = idx & 31;
        *(float2*)&sx2[k * PAD2 + r * 2] = make_float2(rx[j], rx[j]);
        swo[k * PAD + r] = rw[j].x;
        sws[k * PAD + r] = rw[j].y;
        sbs[k * PAD + r] = rb[j];
    }
    __syncthreads();

    const ull C3 = pkc(-1.6666667e-1f);
    const ull C5 = pkc( 8.3333333e-3f);

    float acc0[4], acc1[4];          // scalar accs, MUFU path (oo 0,1)
    ull   accP[4];                   // packed accs, poly path (oo 2,3)
    #pragma unroll
    for (int bb = 0; bb < 4; bb++) { acc0[bb] = 0.f; acc1[bb] = 0.f; accP[bb] = 0ull; }

    for (int k0 = 0; k0 < IN_DIM; k0 += BK) {
        if (k0 + BK < IN_DIM) {
            #pragma unroll
            for (int j = 0; j < 8; j++) {
                int idx = tid + j * 256;
                int r = idx >> 5, k = idx & 31;
                rx[j] = x[(bRow + r) * IN_DIM + k0 + BK + k];
                rw[j] = w2[(oCol + r) * IN_DIM + k0 + BK + k];
                rb[j] = bias[(oCol + r) * (IN_DIM + 1) + k0 + BK + k];
            }
        }

        #pragma unroll 4
        for (int k = 0; k < BK; k++) {
            // MUFU-path operands: oo 0,1 as scalar components
            float2 wsA = *(const float2*)&sws[k * PAD + tx * 4];
            float2 bsA = *(const float2*)&sbs[k * PAD + tx * 4];
            float2 woA = *(const float2*)&swo[k * PAD + tx * 4];
            // poly-path operands: oo 2,3 as packed 64-bit (direct LDS.64, no MOVs)
            F2U wsB; wsB.f = *(const float2*)&sws[k * PAD + tx * 4 + 2];
            F2U bsB; bsB.f = *(const float2*)&sbs[k * PAD + tx * 4 + 2];
            F2U woB; woB.f = *(const float2*)&swo[k * PAD + tx * 4 + 2];

            #pragma unroll
            for (int bb = 0; bb < 4; bb++) {
                F2U xp;  // {x,x}: packed for poly, .f.x scalar for MUFU path
                xp.f = *(const float2*)&sx2[k * PAD2 + (ty * 4 + bb) * 2];

                // ---- MUFU path, scalar (oo 0,1) ----
                float t0 = fmaf(xp.f.x, wsA.x, bsA.x);
                float t1 = fmaf(xp.f.x, wsA.y, bsA.y);
                acc0[bb] = fmaf(sin_mufu(t0), woA.x, acc0[bb]);
                acc1[bb] = fmaf(sin_mufu(t1), woA.y, acc1[bb]);

                // ---- poly path, packed (oo 2,3): sin t = t + c3 t^3 + c5 t^5 ----
                ull t  = fma2_(xp.u, wsB.u, bsB.u);
                ull tt = mul2_(t, t);
                ull r  = fma2_(C5, tt, C3);
                r      = mul2_(r, tt);
                ull s  = fma2_(r, t, t);
                accP[bb] = fma2_(s, woB.u, accP[bb]);
            }
        }

        __syncthreads();
        if (k0 + BK < IN_DIM) {
            #pragma unroll
            for (int j = 0; j < 8; j++) {
                int idx = tid + j * 256;
                int r = idx >> 5, k = idx & 31;
                *(float2*)&sx2[k * PAD2 + r * 2] = make_float2(rx[j], rx[j]);
                swo[k * PAD + r] = rw[j].x;
                sws[k * PAD + r] = rw[j].y;
                sbs[k * PAD + r] = rb[j];
            }
            __syncthreads();
        }
    }

    // ---- epilogue ----
    float bo[4];
    #pragma unroll
    for (int oo = 0; oo < 4; oo++)
        bo[oo] = bias[(oCol + tx * 4 + oo) * (IN_DIM + 1) + IN_DIM];

    #pragma unroll
    for (int bb = 0; bb < 4; bb++) {
        F2U p; p.u = accP[bb];
        float4 v;
        v.x = acc0[bb] + bo[0];
        v.y = acc1[bb] + bo[1];
        v.z = p.f.x   + bo[2];
        v.w = p.f.y   + bo[3];
        *(float4*)&out[(bRow + ty * 4 + bb) * OUT_DIM + oCol + tx * 4] = v;
    }
}

extern "C" void kernel_launch(void* const* d_in, const int* in_sizes, int n_in,
                              void* d_out, int out_size) {
    const float* x      = (const float*)d_in[0];
    const float* weight = (const float*)d_in[1];
    const float* bias   = (const float*)d_in[2];
    float* out          = (float*)d_out;

    dim3 grid(OUT_DIM / BN, B_DIM / BM);  // (8, 16) = 128 CTAs
    trigo_kernel<<<grid, 256>>>(x, weight, bias, out);
}